// round 2
// baseline (speedup 1.0000x reference)
#include <cuda_runtime.h>
#include <cuda_bf16.h>
#include <cstdint>

#define O_NUM 50000
#define T_NUM 200000
#define N_NUM (O_NUM + T_NUM)
#define D_DIM 128

// ---------------- scratch (no allocations allowed) ----------------
__device__ float     g_y[(size_t)N_NUM * D_DIM];   // aggregated rows, 128 MB
__device__ float     g_dinv[N_NUM];
__device__ int       g_counts[O_NUM];
__device__ int       g_offs[O_NUM + 1];
__device__ int       g_cursor[O_NUM];
__device__ int       g_sorted[T_NUM];
__device__ int       g_stride;   // 2 if edges are int32, 4 if int64
__device__ int       g_doff;     // 1 if int32, 2 if int64

// edge accessors: view edges as int32 words. For int64 little-endian data the
// low word at 4t (src) / 4t+2 (dst) holds the value (all values < 2^31).
__device__ __forceinline__ int edge_src(const int* e32, int t, int stride) {
    return e32[(size_t)stride * t];
}
__device__ __forceinline__ int edge_dst(const int* e32, int t, int stride, int doff) {
    return e32[(size_t)stride * t + doff];
}

// ---------------- helpers ----------------
__device__ __forceinline__ const float* row_ptr(int k, const float* obj, const float* pred) {
    return (k < O_NUM) ? (obj + (size_t)k * D_DIM) : (pred + (size_t)(k - O_NUM) * D_DIM);
}

// ---------------- K-1: detect edge dtype (int32 vs int64) ----------------
__global__ void detect_kernel(const int* __restrict__ e32) {
    int acc = 0;
    for (int i = threadIdx.x; i < 4096; i += 32) acc |= e32[2 * i + 1];
    #pragma unroll
    for (int off = 16; off; off >>= 1) acc |= __shfl_xor_sync(0xFFFFFFFFu, acc, off);
    if (threadIdx.x == 0) {
        // nonzero odd words => int32 layout (odd words are dst values)
        // all-zero  odd words => int64 layout (odd words are high words)
        g_stride = acc ? 2 : 4;
        g_doff   = acc ? 1 : 2;
    }
}

// ---------------- K0: zero counters ----------------
__global__ void zero_kernel() {
    int i = blockIdx.x * blockDim.x + threadIdx.x;
    if (i < O_NUM) { g_counts[i] = 0; g_cursor[i] = 0; }
}

// ---------------- K1: histogram of edges[:,1] ----------------
__global__ void hist_kernel(const int* __restrict__ e32) {
    int t = blockIdx.x * blockDim.x + threadIdx.x;
    if (t < T_NUM) {
        int d = edge_dst(e32, t, g_stride, g_doff);
        atomicAdd(&g_counts[d], 1);
    }
}

// ---------------- K2: exclusive scan over O_NUM bins (single CTA) ----------------
__global__ void scan_kernel() {
    __shared__ int sh[1024];
    __shared__ int carry_s;
    if (threadIdx.x == 0) carry_s = 0;
    __syncthreads();
    for (int base = 0; base < O_NUM; base += 1024) {
        int i = base + threadIdx.x;
        int v = (i < O_NUM) ? g_counts[i] : 0;
        sh[threadIdx.x] = v;
        __syncthreads();
        #pragma unroll
        for (int off = 1; off < 1024; off <<= 1) {
            int t = 0;
            if (threadIdx.x >= off) t = sh[threadIdx.x - off];
            __syncthreads();
            if (threadIdx.x >= off) sh[threadIdx.x] += t;
            __syncthreads();
        }
        int incl = sh[threadIdx.x];
        int carry = carry_s;
        if (i < O_NUM) g_offs[i] = incl - v + carry;
        __syncthreads();
        if (threadIdx.x == 1023) carry_s = carry + sh[1023];
        __syncthreads();
    }
    if (threadIdx.x == 0) g_offs[O_NUM] = carry_s;
}

// ---------------- K3: dinv (analytic degree) ----------------
__global__ void dinv_kernel() {
    int n = blockIdx.x * blockDim.x + threadIdx.x;
    if (n >= N_NUM) return;
    float deg;
    if (n < O_NUM)       deg = 2.0f + (float)g_counts[n];  // self + group1 + group2 hits
    else if (n < T_NUM)  deg = 2.0f;                        // self + group1
    else                 deg = 1.0f;                        // self only
    g_dinv[n] = rsqrtf(deg);
}

// ---------------- K4: counting-sort scatter (build CSR of group-2 sources) ----------------
__global__ void csr_scatter_kernel(const int* __restrict__ e32) {
    int t = blockIdx.x * blockDim.x + threadIdx.x;
    if (t < T_NUM) {
        int d = edge_dst(e32, t, g_stride, g_doff);
        int pos = g_offs[d] + atomicAdd(&g_cursor[d], 1);
        g_sorted[pos] = t;
    }
}

// ---------------- K5: aggregation, one warp per node row ----------------
__global__ void aggregate_kernel(const float* __restrict__ obj,
                                 const float* __restrict__ pred,
                                 const int* __restrict__ e32) {
    int gwarp = (blockIdx.x * blockDim.x + threadIdx.x) >> 5;
    int lane  = threadIdx.x & 31;
    if (gwarp >= N_NUM) return;
    int n = gwarp;
    int stride = g_stride;
    float dn = g_dinv[n];

    // self loop
    const float4* xn = reinterpret_cast<const float4*>(row_ptr(n, obj, pred));
    float4 a = xn[lane];
    float4 acc;
    acc.x = a.x * dn; acc.y = a.y * dn; acc.z = a.z * dn; acc.w = a.w * dn;

    // group 1: dst == n (n < T), src = edges[n,0] (object)
    if (n < T_NUM) {
        int s = edge_src(e32, n, stride);
        float ds = g_dinv[s];
        const float4* xs = reinterpret_cast<const float4*>(obj + (size_t)s * D_DIM);
        float4 v = xs[lane];
        acc.x = fmaf(v.x, ds, acc.x);
        acc.y = fmaf(v.y, ds, acc.y);
        acc.z = fmaf(v.z, ds, acc.z);
        acc.w = fmaf(v.w, ds, acc.w);
    }

    // group 2: dst == n (n < O), sources = sorted bucket (each src is node k)
    if (n < O_NUM) {
        int beg = g_offs[n];
        int end = g_offs[n + 1];
        for (int j = beg; j < end; j++) {
            int k = g_sorted[j];
            float dk = g_dinv[k];
            const float4* xk = reinterpret_cast<const float4*>(row_ptr(k, obj, pred));
            float4 v = xk[lane];
            acc.x = fmaf(v.x, dk, acc.x);
            acc.y = fmaf(v.y, dk, acc.y);
            acc.z = fmaf(v.z, dk, acc.z);
            acc.w = fmaf(v.w, dk, acc.w);
        }
    }

    // final scale by dinv[dst]
    acc.x *= dn; acc.y *= dn; acc.z *= dn; acc.w *= dn;
    reinterpret_cast<float4*>(g_y + (size_t)n * D_DIM)[lane] = acc;
}

// ---------------- K6: out = Y @ W^T + b  (fp32 SGEMM, 64x128 tile) ----------------
__global__ __launch_bounds__(256) void gemm_kernel(const float* __restrict__ W,
                                                   const float* __restrict__ bias,
                                                   float* __restrict__ out) {
    __shared__ float As[16][68];    // [k][row], padded
    __shared__ float Bs[16][132];   // [k][col], padded

    const float* Y = g_y;
    int tid = threadIdx.x;
    int rowbase = blockIdx.x * 64;
    int tr = tid >> 5;      // 0..7  -> rows tr*8 .. tr*8+7
    int tc = tid & 31;      // 0..31 -> cols tc*4 .. tc*4+3

    float acc[8][4];
    #pragma unroll
    for (int i = 0; i < 8; i++)
        #pragma unroll
        for (int j = 0; j < 4; j++) acc[i][j] = 0.0f;

    int lrow = tid >> 2;    // 0..63
    int lseg = tid & 3;     // 0..3

    for (int kb = 0; kb < D_DIM; kb += 16) {
        // load Y tile (64 x 16), transposed into As[k][row]
        {
            int grow = rowbase + lrow;
            float4 v = make_float4(0.f, 0.f, 0.f, 0.f);
            if (grow < N_NUM)
                v = *reinterpret_cast<const float4*>(Y + (size_t)grow * D_DIM + kb + lseg * 4);
            As[lseg * 4 + 0][lrow] = v.x;
            As[lseg * 4 + 1][lrow] = v.y;
            As[lseg * 4 + 2][lrow] = v.z;
            As[lseg * 4 + 3][lrow] = v.w;
        }
        // load W tile (128 cols x 16 k), transposed into Bs[k][col]
        #pragma unroll
        for (int q = 0; q < 2; q++) {
            int idx = tid + q * 256;
            int j = idx >> 2;
            int seg = idx & 3;
            float4 v = *reinterpret_cast<const float4*>(W + (size_t)j * D_DIM + kb + seg * 4);
            Bs[seg * 4 + 0][j] = v.x;
            Bs[seg * 4 + 1][j] = v.y;
            Bs[seg * 4 + 2][j] = v.z;
            Bs[seg * 4 + 3][j] = v.w;
        }
        __syncthreads();

        #pragma unroll
        for (int kk = 0; kk < 16; kk++) {
            float4 b0 = *reinterpret_cast<const float4*>(&Bs[kk][tc * 4]);
            float4 a0 = *reinterpret_cast<const float4*>(&As[kk][tr * 8]);
            float4 a1 = *reinterpret_cast<const float4*>(&As[kk][tr * 8 + 4]);
            float av[8] = {a0.x, a0.y, a0.z, a0.w, a1.x, a1.y, a1.z, a1.w};
            float bv[4] = {b0.x, b0.y, b0.z, b0.w};
            #pragma unroll
            for (int i = 0; i < 8; i++)
                #pragma unroll
                for (int j = 0; j < 4; j++)
                    acc[i][j] = fmaf(av[i], bv[j], acc[i][j]);
        }
        __syncthreads();
    }

    float4 bb = *reinterpret_cast<const float4*>(bias + tc * 4);
    #pragma unroll
    for (int i = 0; i < 8; i++) {
        int grow = rowbase + tr * 8 + i;
        if (grow < N_NUM) {
            float4 o;
            o.x = acc[i][0] + bb.x;
            o.y = acc[i][1] + bb.y;
            o.z = acc[i][2] + bb.z;
            o.w = acc[i][3] + bb.w;
            *reinterpret_cast<float4*>(out + (size_t)grow * D_DIM + tc * 4) = o;
        }
    }
}

// ---------------- launch ----------------
extern "C" void kernel_launch(void* const* d_in, const int* in_sizes, int n_in,
                              void* d_out, int out_size) {
    const float* obj   = (const float*)d_in[0];
    const float* pred  = (const float*)d_in[1];
    const int*   e32   = (const int*)d_in[2];
    const float* W     = (const float*)d_in[3];
    const float* bias  = (const float*)d_in[4];
    float*       out   = (float*)d_out;

    detect_kernel<<<1, 32>>>(e32);
    zero_kernel<<<(O_NUM + 255) / 256, 256>>>();
    hist_kernel<<<(T_NUM + 255) / 256, 256>>>(e32);
    scan_kernel<<<1, 1024>>>();
    dinv_kernel<<<(N_NUM + 255) / 256, 256>>>();
    csr_scatter_kernel<<<(T_NUM + 255) / 256, 256>>>(e32);

    // one warp per node row: 8 warps per 256-thread CTA
    int agg_blocks = (N_NUM + 7) / 8;
    aggregate_kernel<<<agg_blocks, 256>>>(obj, pred, e32);

    int gemm_blocks = (N_NUM + 63) / 64;
    gemm_kernel<<<gemm_blocks, 256>>>(W, bias, out);
}

// round 3
// speedup vs baseline: 1.0735x; 1.0735x over previous
#include <cuda_runtime.h>
#include <cuda_bf16.h>
#include <cstdint>

#define O_NUM 50000
#define T_NUM 200000
#define N_NUM (O_NUM + T_NUM)
#define D_DIM 128

// ---------------- scratch (no allocations allowed) ----------------
__device__ __nv_bfloat16 g_yh[(size_t)N_NUM * D_DIM];   // aggregated rows, hi bf16 (64 MB)
__device__ __nv_bfloat16 g_yl[(size_t)N_NUM * D_DIM];   // aggregated rows, lo bf16 (64 MB)
__device__ __nv_bfloat16 g_wh[D_DIM * D_DIM];
__device__ __nv_bfloat16 g_wl[D_DIM * D_DIM];
__device__ float     g_dinv[N_NUM];
__device__ int       g_counts[O_NUM];
__device__ int       g_offs[O_NUM + 1];
__device__ int       g_cursor[O_NUM];
__device__ int       g_sorted[T_NUM];
__device__ int       g_stride;   // 2 if edges are int32, 4 if int64
__device__ int       g_doff;     // 1 if int32, 2 if int64

__device__ __forceinline__ int edge_src(const int* e32, int t, int stride) {
    return e32[(size_t)stride * t];
}
__device__ __forceinline__ int edge_dst(const int* e32, int t, int stride, int doff) {
    return e32[(size_t)stride * t + doff];
}
__device__ __forceinline__ const float* row_ptr(int k, const float* obj, const float* pred) {
    return (k < O_NUM) ? (obj + (size_t)k * D_DIM) : (pred + (size_t)(k - O_NUM) * D_DIM);
}

// ---------------- K-1: detect edge dtype (int32 vs int64) ----------------
__global__ void detect_kernel(const int* __restrict__ e32) {
    int acc = 0;
    for (int i = threadIdx.x; i < 4096; i += 32) acc |= e32[2 * i + 1];
    #pragma unroll
    for (int off = 16; off; off >>= 1) acc |= __shfl_xor_sync(0xFFFFFFFFu, acc, off);
    if (threadIdx.x == 0) {
        g_stride = acc ? 2 : 4;
        g_doff   = acc ? 1 : 2;
    }
}

// ---------------- K0: zero counters ----------------
__global__ void zero_kernel() {
    int i = blockIdx.x * blockDim.x + threadIdx.x;
    if (i < O_NUM) { g_counts[i] = 0; g_cursor[i] = 0; }
}

// ---------------- K1: histogram of edges[:,1] ----------------
__global__ void hist_kernel(const int* __restrict__ e32) {
    int t = blockIdx.x * blockDim.x + threadIdx.x;
    if (t < T_NUM) {
        int d = edge_dst(e32, t, g_stride, g_doff);
        atomicAdd(&g_counts[d], 1);
    }
}

// ---------------- K2: fast exclusive scan (1 CTA, chunked + warp shuffles) ----------------
__global__ __launch_bounds__(1024) void scan_kernel() {
    const int CH = (O_NUM + 1023) / 1024;  // 49
    int t = threadIdx.x;
    int lane = t & 31, w = t >> 5;
    int beg = t * CH;
    int end = beg + CH; if (end > O_NUM) end = O_NUM;

    int s = 0;
    for (int i = beg; i < end && i >= beg; i++) s += g_counts[i];

    // inclusive warp scan of thread sums
    int v = s;
    #pragma unroll
    for (int off = 1; off < 32; off <<= 1) {
        int n = __shfl_up_sync(0xFFFFFFFFu, v, off);
        if (lane >= off) v += n;
    }
    __shared__ int wsum[32];
    if (lane == 31) wsum[w] = v;
    __syncthreads();
    if (w == 0) {
        int x = wsum[lane];
        #pragma unroll
        for (int off = 1; off < 32; off <<= 1) {
            int n = __shfl_up_sync(0xFFFFFFFFu, x, off);
            if (lane >= off) x += n;
        }
        wsum[lane] = x;
    }
    __syncthreads();
    int excl = v - s + (w ? wsum[w - 1] : 0);

    int run = excl;
    for (int i = beg; i < end && i >= beg; i++) {
        g_offs[i] = run;
        run += g_counts[i];
    }
    if (t == 1023) g_offs[O_NUM] = excl;  // all bins < beg(1023*49) > O_NUM, so excl == total
}

// ---------------- K3: dinv (analytic degree) ----------------
__global__ void dinv_kernel() {
    int n = blockIdx.x * blockDim.x + threadIdx.x;
    if (n >= N_NUM) return;
    float deg;
    if (n < O_NUM)       deg = 2.0f + (float)g_counts[n];
    else if (n < T_NUM)  deg = 2.0f;
    else                 deg = 1.0f;
    g_dinv[n] = rsqrtf(deg);
}

// ---------------- K4: counting-sort scatter (build CSR of group-2 sources) ----------------
__global__ void csr_scatter_kernel(const int* __restrict__ e32) {
    int t = blockIdx.x * blockDim.x + threadIdx.x;
    if (t < T_NUM) {
        int d = edge_dst(e32, t, g_stride, g_doff);
        int pos = g_offs[d] + atomicAdd(&g_cursor[d], 1);
        g_sorted[pos] = t;
    }
}

// ---------------- K5: aggregation, one warp per node row, bf16 hi/lo output ----------------
__global__ void aggregate_kernel(const float* __restrict__ obj,
                                 const float* __restrict__ pred,
                                 const int* __restrict__ e32) {
    int gwarp = (blockIdx.x * blockDim.x + threadIdx.x) >> 5;
    int lane  = threadIdx.x & 31;
    if (gwarp >= N_NUM) return;
    int n = gwarp;
    int stride = g_stride;
    float dn = g_dinv[n];

    const float4* xn = reinterpret_cast<const float4*>(row_ptr(n, obj, pred));
    float4 a = xn[lane];
    float4 acc;
    acc.x = a.x * dn; acc.y = a.y * dn; acc.z = a.z * dn; acc.w = a.w * dn;

    if (n < T_NUM) {
        int s = edge_src(e32, n, stride);
        float ds = g_dinv[s];
        const float4* xs = reinterpret_cast<const float4*>(obj + (size_t)s * D_DIM);
        float4 v = xs[lane];
        acc.x = fmaf(v.x, ds, acc.x);
        acc.y = fmaf(v.y, ds, acc.y);
        acc.z = fmaf(v.z, ds, acc.z);
        acc.w = fmaf(v.w, ds, acc.w);
    }

    if (n < O_NUM) {
        int beg = g_offs[n];
        int end = g_offs[n + 1];
        for (int j = beg; j < end; j++) {
            int k = g_sorted[j];
            float dk = g_dinv[k];
            const float4* xk = reinterpret_cast<const float4*>(row_ptr(k, obj, pred));
            float4 v = xk[lane];
            acc.x = fmaf(v.x, dk, acc.x);
            acc.y = fmaf(v.y, dk, acc.y);
            acc.z = fmaf(v.z, dk, acc.z);
            acc.w = fmaf(v.w, dk, acc.w);
        }
    }

    acc.x *= dn; acc.y *= dn; acc.z *= dn; acc.w *= dn;

    // split into hi/lo bf16
    float v4[4] = {acc.x, acc.y, acc.z, acc.w};
    alignas(8) __nv_bfloat16 h[4];
    alignas(8) __nv_bfloat16 l[4];
    #pragma unroll
    for (int i = 0; i < 4; i++) {
        h[i] = __float2bfloat16(v4[i]);
        l[i] = __float2bfloat16(v4[i] - __bfloat162float(h[i]));
    }
    size_t base = (size_t)n * D_DIM + lane * 4;
    *reinterpret_cast<uint2*>(g_yh + base) = *reinterpret_cast<const uint2*>(h);
    *reinterpret_cast<uint2*>(g_yl + base) = *reinterpret_cast<const uint2*>(l);
}

// ---------------- K5b: split W into hi/lo bf16 ----------------
__global__ void wconv_kernel(const float* __restrict__ W) {
    int i = blockIdx.x * blockDim.x + threadIdx.x;
    if (i < D_DIM * D_DIM) {
        float w = W[i];
        __nv_bfloat16 h = __float2bfloat16(w);
        g_wh[i] = h;
        g_wl[i] = __float2bfloat16(w - __bfloat162float(h));
    }
}

// ---------------- K6: out = Y @ W^T + b  via bf16-split mma.sync ----------------
__device__ __forceinline__ void mma16816(float c[4], const uint32_t a[4], const uint32_t b[2]) {
    asm("mma.sync.aligned.m16n8k16.row.col.f32.bf16.bf16.f32 "
        "{%0,%1,%2,%3}, {%4,%5,%6,%7}, {%8,%9}, {%0,%1,%2,%3};"
        : "+f"(c[0]), "+f"(c[1]), "+f"(c[2]), "+f"(c[3])
        : "r"(a[0]), "r"(a[1]), "r"(a[2]), "r"(a[3]), "r"(b[0]), "r"(b[1]));
}

__global__ __launch_bounds__(256) void gemm_mma_kernel(const float* __restrict__ bias,
                                                       float* __restrict__ out) {
    int tid  = threadIdx.x;
    int warp = tid >> 5, lane = tid & 31;
    int g  = lane >> 2;      // 0..7
    int tg = lane & 3;       // 0..3
    int warpM = warp >> 1;   // 0..3
    int warpN = warp & 1;    // 0..1
    int rowbase = blockIdx.x * 128 + warpM * 32;
    int colbase = warpN * 64;

    float c[2][8][4];
    #pragma unroll
    for (int m = 0; m < 2; m++)
        #pragma unroll
        for (int n = 0; n < 8; n++)
            #pragma unroll
            for (int q = 0; q < 4; q++) c[m][n][q] = 0.0f;

    float2 bv[8];
    #pragma unroll
    for (int n = 0; n < 8; n++)
        bv[n] = *reinterpret_cast<const float2*>(bias + colbase + n * 8 + tg * 2);

    #pragma unroll
    for (int kb = 0; kb < 8; kb++) {
        int k = kb * 16;

        uint32_t ah[2][4], al[2][4];
        #pragma unroll
        for (int m = 0; m < 2; m++) {
            int r0 = rowbase + m * 16 + g;
            int r1 = r0 + 8;
            size_t o0 = (size_t)r0 * D_DIM + k + tg * 2;
            size_t o1 = (size_t)r1 * D_DIM + k + tg * 2;
            bool p0 = r0 < N_NUM, p1 = r1 < N_NUM;
            ah[m][0] = p0 ? *reinterpret_cast<const uint32_t*>(g_yh + o0)     : 0u;
            ah[m][1] = p1 ? *reinterpret_cast<const uint32_t*>(g_yh + o1)     : 0u;
            ah[m][2] = p0 ? *reinterpret_cast<const uint32_t*>(g_yh + o0 + 8) : 0u;
            ah[m][3] = p1 ? *reinterpret_cast<const uint32_t*>(g_yh + o1 + 8) : 0u;
            al[m][0] = p0 ? *reinterpret_cast<const uint32_t*>(g_yl + o0)     : 0u;
            al[m][1] = p1 ? *reinterpret_cast<const uint32_t*>(g_yl + o1)     : 0u;
            al[m][2] = p0 ? *reinterpret_cast<const uint32_t*>(g_yl + o0 + 8) : 0u;
            al[m][3] = p1 ? *reinterpret_cast<const uint32_t*>(g_yl + o1 + 8) : 0u;
        }

        uint32_t bh[8][2], bl[8][2];
        #pragma unroll
        for (int n = 0; n < 8; n++) {
            int cw = colbase + n * 8 + g;
            size_t ob = (size_t)cw * D_DIM + k + tg * 2;
            bh[n][0] = *reinterpret_cast<const uint32_t*>(g_wh + ob);
            bh[n][1] = *reinterpret_cast<const uint32_t*>(g_wh + ob + 8);
            bl[n][0] = *reinterpret_cast<const uint32_t*>(g_wl + ob);
            bl[n][1] = *reinterpret_cast<const uint32_t*>(g_wl + ob + 8);
        }

        #pragma unroll
        for (int m = 0; m < 2; m++)
            #pragma unroll
            for (int n = 0; n < 8; n++) {
                mma16816(c[m][n], ah[m], bh[n]);
                mma16816(c[m][n], ah[m], bl[n]);
                mma16816(c[m][n], al[m], bh[n]);
            }
    }

    #pragma unroll
    for (int m = 0; m < 2; m++) {
        int r0 = rowbase + m * 16 + g;
        int r1 = r0 + 8;
        #pragma unroll
        for (int n = 0; n < 8; n++) {
            int co = colbase + n * 8 + tg * 2;
            if (r0 < N_NUM) {
                float2 o = make_float2(c[m][n][0] + bv[n].x, c[m][n][1] + bv[n].y);
                *reinterpret_cast<float2*>(out + (size_t)r0 * D_DIM + co) = o;
            }
            if (r1 < N_NUM) {
                float2 o = make_float2(c[m][n][2] + bv[n].x, c[m][n][3] + bv[n].y);
                *reinterpret_cast<float2*>(out + (size_t)r1 * D_DIM + co) = o;
            }
        }
    }
}

// ---------------- launch ----------------
extern "C" void kernel_launch(void* const* d_in, const int* in_sizes, int n_in,
                              void* d_out, int out_size) {
    const float* obj   = (const float*)d_in[0];
    const float* pred  = (const float*)d_in[1];
    const int*   e32   = (const int*)d_in[2];
    const float* W     = (const float*)d_in[3];
    const float* bias  = (const float*)d_in[4];
    float*       out   = (float*)d_out;

    detect_kernel<<<1, 32>>>(e32);
    zero_kernel<<<(O_NUM + 255) / 256, 256>>>();
    hist_kernel<<<(T_NUM + 255) / 256, 256>>>(e32);
    scan_kernel<<<1, 1024>>>();
    dinv_kernel<<<(N_NUM + 255) / 256, 256>>>();
    csr_scatter_kernel<<<(T_NUM + 255) / 256, 256>>>(e32);
    wconv_kernel<<<(D_DIM * D_DIM + 255) / 256, 256>>>(W);

    int agg_blocks = (N_NUM + 7) / 8;
    aggregate_kernel<<<agg_blocks, 256>>>(obj, pred, e32);

    int gemm_blocks = (N_NUM + 127) / 128;   // 1954
    gemm_mma_kernel<<<gemm_blocks, 256>>>(bias, out);
}

// round 4
// speedup vs baseline: 1.5112x; 1.4077x over previous
#include <cuda_runtime.h>
#include <cuda_bf16.h>
#include <cstdint>

#define O_NUM 50000
#define T_NUM 200000
#define N_NUM (O_NUM + T_NUM)
#define D_DIM 128
#define NPART 196           // ceil(O_NUM/256)
#define RSQRT2F 0.7071067811865476f

// ---------------- scratch (no allocations allowed) ----------------
__device__ __nv_bfloat16 g_yh[(size_t)N_NUM * D_DIM];
__device__ __nv_bfloat16 g_yl[(size_t)N_NUM * D_DIM];
__device__ __nv_bfloat16 g_wh[D_DIM * D_DIM];
__device__ __nv_bfloat16 g_wl[D_DIM * D_DIM];
__device__ float     g_dinv[O_NUM];     // only objects are data-dependent
__device__ int       g_counts[O_NUM];
__device__ int       g_offs[O_NUM + 1];
__device__ int       g_cursor[O_NUM];
__device__ int       g_sorted[T_NUM];
__device__ int       g_part[NPART];
__device__ int       g_stride;
__device__ int       g_doff;

__device__ __forceinline__ int edge_src(const int* e32, int t, int stride) {
    return __ldg(e32 + (size_t)stride * t);
}
__device__ __forceinline__ int edge_dst(const int* e32, int t, int stride, int doff) {
    return __ldg(e32 + (size_t)stride * t + doff);
}
__device__ __forceinline__ const float* row_ptr(int k, const float* obj, const float* pred) {
    return (k < O_NUM) ? (obj + (size_t)k * D_DIM) : (pred + (size_t)(k - O_NUM) * D_DIM);
}

// ---------------- K-1: detect edge dtype (int32 vs int64) ----------------
__global__ void detect_kernel(const int* __restrict__ e32) {
    int acc = 0;
    for (int i = threadIdx.x; i < 4096; i += 32) acc |= e32[2 * i + 1];
    #pragma unroll
    for (int off = 16; off; off >>= 1) acc |= __shfl_xor_sync(0xFFFFFFFFu, acc, off);
    if (threadIdx.x == 0) {
        g_stride = acc ? 2 : 4;
        g_doff   = acc ? 1 : 2;
    }
}

// ---------------- K0: zero counters ----------------
__global__ void zero_kernel() {
    int i = blockIdx.x * blockDim.x + threadIdx.x;
    if (i < O_NUM) { g_counts[i] = 0; g_cursor[i] = 0; }
}

// ---------------- K1: histogram of edges[:,1] ----------------
__global__ void hist_kernel(const int* __restrict__ e32) {
    int t = blockIdx.x * blockDim.x + threadIdx.x;
    if (t < T_NUM) {
        int d = edge_dst(e32, t, g_stride, g_doff);
        atomicAdd(&g_counts[d], 1);
    }
}

// ---------------- K2a: per-block exclusive scan (coalesced) ----------------
__global__ __launch_bounds__(256) void scan_block_kernel() {
    int t = threadIdx.x;
    int i = blockIdx.x * 256 + t;
    int lane = t & 31, w = t >> 5;
    int v = (i < O_NUM) ? g_counts[i] : 0;

    int iv = v;
    #pragma unroll
    for (int off = 1; off < 32; off <<= 1) {
        int n = __shfl_up_sync(0xFFFFFFFFu, iv, off);
        if (lane >= off) iv += n;
    }
    __shared__ int ws[8];
    if (lane == 31) ws[w] = iv;
    __syncthreads();
    if (w == 0 && lane < 8) {
        int x = ws[lane];
        #pragma unroll
        for (int off = 1; off < 8; off <<= 1) {
            int n = __shfl_up_sync(0x000000FFu, x, off);
            if (lane >= off) x += n;
        }
        ws[lane] = x;
    }
    __syncthreads();
    int excl = iv - v + (w ? ws[w - 1] : 0);
    if (i < O_NUM) g_offs[i] = excl;           // exclusive within block (temp)
    if (t == 255) g_part[blockIdx.x] = excl + v;
}

// ---------------- K2b: scan 196 block partials (1 small CTA) ----------------
__global__ __launch_bounds__(256) void scan_part_kernel() {
    int t = threadIdx.x;
    int lane = t & 31, w = t >> 5;
    int v = (t < NPART) ? g_part[t] : 0;
    int iv = v;
    #pragma unroll
    for (int off = 1; off < 32; off <<= 1) {
        int n = __shfl_up_sync(0xFFFFFFFFu, iv, off);
        if (lane >= off) iv += n;
    }
    __shared__ int ws[8];
    if (lane == 31) ws[w] = iv;
    __syncthreads();
    if (w == 0 && lane < 8) {
        int x = ws[lane];
        #pragma unroll
        for (int off = 1; off < 8; off <<= 1) {
            int n = __shfl_up_sync(0x000000FFu, x, off);
            if (lane >= off) x += n;
        }
        ws[lane] = x;
    }
    __syncthreads();
    int excl = iv - v + (w ? ws[w - 1] : 0);
    if (t < NPART) g_part[t] = excl;
    if (t == NPART - 1) g_offs[O_NUM] = excl + v;   // total
}

// ---------------- K2c: add block base + fill dinv for objects ----------------
__global__ __launch_bounds__(256) void scan_add_kernel() {
    int i = blockIdx.x * 256 + threadIdx.x;
    if (i < O_NUM) {
        g_offs[i] += g_part[blockIdx.x];
        g_dinv[i] = rsqrtf(2.0f + (float)g_counts[i]);
    }
}

// ---------------- K4: counting-sort scatter (build CSR of group-2 sources) ----------------
__global__ void csr_scatter_kernel(const int* __restrict__ e32) {
    int t = blockIdx.x * blockDim.x + threadIdx.x;
    if (t < T_NUM) {
        int d = edge_dst(e32, t, g_stride, g_doff);
        int pos = g_offs[d] + atomicAdd(&g_cursor[d], 1);
        g_sorted[pos] = t;
    }
}

// ---------------- K5: aggregation, one warp per node row, bf16 hi/lo output ----------------
__device__ __forceinline__ float node_dinv(int n) {
    return (n < O_NUM) ? g_dinv[n] : ((n < T_NUM) ? RSQRT2F : 1.0f);
}

__global__ void aggregate_kernel(const float* __restrict__ obj,
                                 const float* __restrict__ pred,
                                 const int* __restrict__ e32) {
    int gwarp = (blockIdx.x * blockDim.x + threadIdx.x) >> 5;
    int lane  = threadIdx.x & 31;
    if (gwarp >= N_NUM) return;
    int n = gwarp;
    int stride = g_stride;
    float dn = node_dinv(n);

    const float4* xn = reinterpret_cast<const float4*>(row_ptr(n, obj, pred));
    float4 a = __ldg(xn + lane);
    float4 acc;
    acc.x = a.x * dn; acc.y = a.y * dn; acc.z = a.z * dn; acc.w = a.w * dn;

    // group 1: dst == n (n < T), src = edges[n,0] (object)
    if (n < T_NUM) {
        int s = edge_src(e32, n, stride);
        float ds = g_dinv[s];
        const float4* xs = reinterpret_cast<const float4*>(obj + (size_t)s * D_DIM);
        float4 v = __ldg(xs + lane);
        acc.x = fmaf(v.x, ds, acc.x);
        acc.y = fmaf(v.y, ds, acc.y);
        acc.z = fmaf(v.z, ds, acc.z);
        acc.w = fmaf(v.w, ds, acc.w);
    }

    // group 2: dst == n (n < O), sources = sorted bucket (each src is node k)
    if (n < O_NUM) {
        int beg = g_offs[n];
        int end = g_offs[n + 1];
        if (beg < end) {
            int kNext = g_sorted[beg];
            for (int j = beg; j < end; j++) {
                int k = kNext;
                if (j + 1 < end) kNext = g_sorted[j + 1];
                float dk = (k < O_NUM) ? g_dinv[k] : RSQRT2F;
                const float4* xk = reinterpret_cast<const float4*>(row_ptr(k, obj, pred));
                float4 v = __ldg(xk + lane);
                acc.x = fmaf(v.x, dk, acc.x);
                acc.y = fmaf(v.y, dk, acc.y);
                acc.z = fmaf(v.z, dk, acc.z);
                acc.w = fmaf(v.w, dk, acc.w);
            }
        }
    }

    acc.x *= dn; acc.y *= dn; acc.z *= dn; acc.w *= dn;

    float v4[4] = {acc.x, acc.y, acc.z, acc.w};
    alignas(8) __nv_bfloat16 h[4];
    alignas(8) __nv_bfloat16 l[4];
    #pragma unroll
    for (int i = 0; i < 4; i++) {
        h[i] = __float2bfloat16(v4[i]);
        l[i] = __float2bfloat16(v4[i] - __bfloat162float(h[i]));
    }
    size_t base = (size_t)n * D_DIM + lane * 4;
    *reinterpret_cast<uint2*>(g_yh + base) = *reinterpret_cast<const uint2*>(h);
    *reinterpret_cast<uint2*>(g_yl + base) = *reinterpret_cast<const uint2*>(l);
}

// ---------------- K5b: split W into hi/lo bf16 ----------------
__global__ void wconv_kernel(const float* __restrict__ W) {
    int i = blockIdx.x * blockDim.x + threadIdx.x;
    if (i < D_DIM * D_DIM) {
        float w = W[i];
        __nv_bfloat16 h = __float2bfloat16(w);
        g_wh[i] = h;
        g_wl[i] = __float2bfloat16(w - __bfloat162float(h));
    }
}

// ---------------- K6: out = Y @ W^T + b  via bf16-split mma, smem-staged ----------------
__device__ __forceinline__ void mma16816(float c[4], const uint32_t a[4], const uint32_t b[2]) {
    asm("mma.sync.aligned.m16n8k16.row.col.f32.bf16.bf16.f32 "
        "{%0,%1,%2,%3}, {%4,%5,%6,%7}, {%8,%9}, {%0,%1,%2,%3};"
        : "+f"(c[0]), "+f"(c[1]), "+f"(c[2]), "+f"(c[3])
        : "r"(a[0]), "r"(a[1]), "r"(a[2]), "r"(a[3]), "r"(b[0]), "r"(b[1]));
}

#define LDSY 136   // 128 + 8 bf16 pad -> row stride 68 words -> conflict-free frags
#define TILE_BYTES (128 * LDSY * 2)

__device__ __forceinline__ uint32_t lds32(const __nv_bfloat16* p) {
    return *reinterpret_cast<const uint32_t*>(p);
}

extern __shared__ char sm_raw[];

__global__ __launch_bounds__(256) void gemm_mma_kernel(const float* __restrict__ bias,
                                                       float* __restrict__ out) {
    __nv_bfloat16* sYh = reinterpret_cast<__nv_bfloat16*>(sm_raw);
    __nv_bfloat16* sYl = sYh + 128 * LDSY;
    __nv_bfloat16* sWh = sYl + 128 * LDSY;
    __nv_bfloat16* sWl = sWh + 128 * LDSY;

    int tid  = threadIdx.x;
    int warp = tid >> 5, lane = tid & 31;
    int g  = lane >> 2;
    int tg = lane & 3;
    int rowbase = blockIdx.x * 128;

    // stage W (both halves), coalesced uint4
    #pragma unroll
    for (int it = 0; it < 8; it++) {
        int r = it * 16 + (tid >> 4);
        int cseg = tid & 15;               // 16 x 8 bf16 segments per row
        uint4 vh = *reinterpret_cast<const uint4*>(g_wh + r * D_DIM + cseg * 8);
        uint4 vl = *reinterpret_cast<const uint4*>(g_wl + r * D_DIM + cseg * 8);
        *reinterpret_cast<uint4*>(sWh + r * LDSY + cseg * 8) = vh;
        *reinterpret_cast<uint4*>(sWl + r * LDSY + cseg * 8) = vl;
    }
    // stage Y tile (128 rows), zero-fill OOB rows
    #pragma unroll
    for (int it = 0; it < 8; it++) {
        int r = it * 16 + (tid >> 4);
        int cseg = tid & 15;
        int grow = rowbase + r;
        uint4 vh = make_uint4(0u, 0u, 0u, 0u), vl = vh;
        if (grow < N_NUM) {
            vh = *reinterpret_cast<const uint4*>(g_yh + (size_t)grow * D_DIM + cseg * 8);
            vl = *reinterpret_cast<const uint4*>(g_yl + (size_t)grow * D_DIM + cseg * 8);
        }
        *reinterpret_cast<uint4*>(sYh + r * LDSY + cseg * 8) = vh;
        *reinterpret_cast<uint4*>(sYl + r * LDSY + cseg * 8) = vl;
    }
    __syncthreads();

    // each warp: 16 rows x 128 cols
    const __nv_bfloat16* aH0 = sYh + (warp * 16 + g) * LDSY;
    const __nv_bfloat16* aL0 = sYl + (warp * 16 + g) * LDSY;

    float c[16][4];
    #pragma unroll
    for (int n = 0; n < 16; n++)
        #pragma unroll
        for (int q = 0; q < 4; q++) c[n][q] = 0.0f;

    #pragma unroll
    for (int kt = 0; kt < 8; kt++) {
        int k = kt * 16;
        uint32_t ah[4], al[4];
        ah[0] = lds32(aH0 + k + tg * 2);
        ah[1] = lds32(aH0 + 8 * LDSY + k + tg * 2);
        ah[2] = lds32(aH0 + k + 8 + tg * 2);
        ah[3] = lds32(aH0 + 8 * LDSY + k + 8 + tg * 2);
        al[0] = lds32(aL0 + k + tg * 2);
        al[1] = lds32(aL0 + 8 * LDSY + k + tg * 2);
        al[2] = lds32(aL0 + k + 8 + tg * 2);
        al[3] = lds32(aL0 + 8 * LDSY + k + 8 + tg * 2);

        #pragma unroll
        for (int n = 0; n < 16; n++) {
            const __nv_bfloat16* bH = sWh + (n * 8 + g) * LDSY + k + tg * 2;
            const __nv_bfloat16* bL = sWl + (n * 8 + g) * LDSY + k + tg * 2;
            uint32_t bh[2] = { lds32(bH), lds32(bH + 8) };
            uint32_t bl[2] = { lds32(bL), lds32(bL + 8) };
            mma16816(c[n], ah, bh);
            mma16816(c[n], al, bh);
            mma16816(c[n], ah, bl);
        }
    }

    int r0 = rowbase + warp * 16 + g;
    int r1 = r0 + 8;
    #pragma unroll
    for (int n = 0; n < 16; n++) {
        int col = n * 8 + tg * 2;
        float2 bb = *reinterpret_cast<const float2*>(bias + col);
        if (r0 < N_NUM) {
            float2 o = make_float2(c[n][0] + bb.x, c[n][1] + bb.y);
            *reinterpret_cast<float2*>(out + (size_t)r0 * D_DIM + col) = o;
        }
        if (r1 < N_NUM) {
            float2 o = make_float2(c[n][2] + bb.x, c[n][3] + bb.y);
            *reinterpret_cast<float2*>(out + (size_t)r1 * D_DIM + col) = o;
        }
    }
}

// ---------------- launch ----------------
extern "C" void kernel_launch(void* const* d_in, const int* in_sizes, int n_in,
                              void* d_out, int out_size) {
    const float* obj   = (const float*)d_in[0];
    const float* pred  = (const float*)d_in[1];
    const int*   e32   = (const int*)d_in[2];
    const float* W     = (const float*)d_in[3];
    const float* bias  = (const float*)d_in[4];
    float*       out   = (float*)d_out;

    cudaFuncSetAttribute(gemm_mma_kernel,
                         cudaFuncAttributeMaxDynamicSharedMemorySize, 4 * TILE_BYTES);

    detect_kernel<<<1, 32>>>(e32);
    zero_kernel<<<NPART, 256>>>();
    hist_kernel<<<(T_NUM + 255) / 256, 256>>>(e32);
    scan_block_kernel<<<NPART, 256>>>();
    scan_part_kernel<<<1, 256>>>();
    scan_add_kernel<<<NPART, 256>>>();
    csr_scatter_kernel<<<(T_NUM + 255) / 256, 256>>>(e32);
    wconv_kernel<<<(D_DIM * D_DIM + 255) / 256, 256>>>(W);

    int agg_blocks = (N_NUM + 7) / 8;
    aggregate_kernel<<<agg_blocks, 256>>>(obj, pred, e32);

    int gemm_blocks = (N_NUM + 127) / 128;
    gemm_mma_kernel<<<gemm_blocks, 256, 4 * TILE_BYTES>>>(bias, out);
}

// round 5
// speedup vs baseline: 1.5648x; 1.0354x over previous
#include <cuda_runtime.h>
#include <cuda_bf16.h>
#include <cstdint>

#define O_NUM 50000
#define T_NUM 200000
#define N_NUM (O_NUM + T_NUM)
#define D_DIM 128
#define NPART 196           // ceil(O_NUM/256)
#define WBLK  64            // wconv blocks (16384/256)
#define RSQRT2F 0.7071067811865476f

// ---------------- scratch (no allocations allowed) ----------------
__device__ __nv_bfloat16 g_yh[(size_t)N_NUM * D_DIM];
__device__ __nv_bfloat16 g_yl[(size_t)N_NUM * D_DIM];
__device__ __nv_bfloat16 g_wh[D_DIM * D_DIM];
__device__ __nv_bfloat16 g_wl[D_DIM * D_DIM];
__device__ float     g_dinv[O_NUM];
__device__ int       g_counts[O_NUM];
__device__ int       g_offs[O_NUM + 1];
__device__ int       g_cursor[O_NUM];
__device__ int       g_sorted[T_NUM];
__device__ int       g_part[NPART];
__device__ int       g_stride;
__device__ int       g_doff;

__device__ __forceinline__ int edge_src(const int* e32, int t, int stride) {
    return __ldg(e32 + (size_t)stride * t);
}
__device__ __forceinline__ int edge_dst(const int* e32, int t, int stride, int doff) {
    return __ldg(e32 + (size_t)stride * t + doff);
}
__device__ __forceinline__ const float* row_ptr(int k, const float* obj, const float* pred) {
    return (k < O_NUM) ? (obj + (size_t)k * D_DIM) : (pred + (size_t)(k - O_NUM) * D_DIM);
}

// ---------------- K1: prep = zero counters + W split + edge-dtype detect ----------------
__global__ void prep_kernel(const float* __restrict__ W, const int* __restrict__ e32) {
    int b = blockIdx.x;
    if (b < NPART) {
        int i = b * 256 + threadIdx.x;
        if (i < O_NUM) { g_counts[i] = 0; g_cursor[i] = 0; }
    } else if (b < NPART + WBLK) {
        int i = (b - NPART) * 256 + threadIdx.x;
        float w = W[i];
        __nv_bfloat16 h = __float2bfloat16(w);
        g_wh[i] = h;
        g_wl[i] = __float2bfloat16(w - __bfloat162float(h));
    } else {
        if (threadIdx.x < 32) {
            int acc = 0;
            for (int i = threadIdx.x; i < 4096; i += 32) acc |= e32[2 * i + 1];
            #pragma unroll
            for (int off = 16; off; off >>= 1) acc |= __shfl_xor_sync(0xFFFFFFFFu, acc, off);
            if (threadIdx.x == 0) {
                g_stride = acc ? 2 : 4;
                g_doff   = acc ? 1 : 2;
            }
        }
    }
}

// ---------------- K2: histogram of edges[:,1] ----------------
__global__ void hist_kernel(const int* __restrict__ e32) {
    int t = blockIdx.x * blockDim.x + threadIdx.x;
    if (t < T_NUM) {
        int d = edge_dst(e32, t, g_stride, g_doff);
        atomicAdd(&g_counts[d], 1);
    }
}

// ---------------- K3: per-block exclusive scan ----------------
__global__ __launch_bounds__(256) void scan_block_kernel() {
    int t = threadIdx.x;
    int i = blockIdx.x * 256 + t;
    int lane = t & 31, w = t >> 5;
    int v = (i < O_NUM) ? g_counts[i] : 0;

    int iv = v;
    #pragma unroll
    for (int off = 1; off < 32; off <<= 1) {
        int n = __shfl_up_sync(0xFFFFFFFFu, iv, off);
        if (lane >= off) iv += n;
    }
    __shared__ int ws[8];
    if (lane == 31) ws[w] = iv;
    __syncthreads();
    if (w == 0 && lane < 8) {
        int x = ws[lane];
        #pragma unroll
        for (int off = 1; off < 8; off <<= 1) {
            int n = __shfl_up_sync(0x000000FFu, x, off);
            if (lane >= off) x += n;
        }
        ws[lane] = x;
    }
    __syncthreads();
    int excl = iv - v + (w ? ws[w - 1] : 0);
    if (i < O_NUM) g_offs[i] = excl;
    if (t == 255) g_part[blockIdx.x] = excl + v;
}

// ---------------- K4: fixup (per-block prefix of partials) + dinv ----------------
__global__ __launch_bounds__(256) void scan_fix_kernel() {
    int b = blockIdx.x;
    int t = threadIdx.x;
    int lane = t & 31, w = t >> 5;

    // reduce g_part[0..b)
    int v = (t < b) ? g_part[t] : 0;
    #pragma unroll
    for (int off = 16; off; off >>= 1) v += __shfl_xor_sync(0xFFFFFFFFu, v, off);
    __shared__ int ws[8];
    if (lane == 0) ws[w] = v;
    __syncthreads();
    __shared__ int base_s;
    if (t == 0) {
        int s = 0;
        #pragma unroll
        for (int q = 0; q < 8; q++) s += ws[q];
        base_s = s;
    }
    __syncthreads();
    int base = base_s;

    int i = b * 256 + t;
    if (i < O_NUM) {
        g_offs[i] += base;
        g_dinv[i] = rsqrtf(2.0f + (float)g_counts[i]);
    }
    if (b == NPART - 1 && t == 0) g_offs[O_NUM] = base + g_part[NPART - 1];
}

// ---------------- K5: counting-sort scatter (build CSR of group-2 sources) ----------------
__global__ void csr_scatter_kernel(const int* __restrict__ e32) {
    int t = blockIdx.x * blockDim.x + threadIdx.x;
    if (t < T_NUM) {
        int d = edge_dst(e32, t, g_stride, g_doff);
        int pos = g_offs[d] + atomicAdd(&g_cursor[d], 1);
        g_sorted[pos] = t;
    }
}

// ---------------- K6: aggregation, warp per row, batched MLP gathers ----------------
__global__ __launch_bounds__(256) void aggregate_kernel(const float* __restrict__ obj,
                                                        const float* __restrict__ pred,
                                                        const int* __restrict__ e32) {
    int gwarp = (blockIdx.x * blockDim.x + threadIdx.x) >> 5;
    int lane  = threadIdx.x & 31;
    if (gwarp >= N_NUM) return;
    int n = gwarp;
    float dn = (n < O_NUM) ? g_dinv[n] : ((n < T_NUM) ? RSQRT2F : 1.0f);

    // issue self + group1 loads up front (independent)
    const float4* xn = reinterpret_cast<const float4*>(row_ptr(n, obj, pred));
    float4 a = __ldg(xn + lane);

    float4 v1 = make_float4(0.f, 0.f, 0.f, 0.f);
    float  ds = 0.0f;
    if (n < T_NUM) {
        int s = edge_src(e32, n, g_stride);
        ds = g_dinv[s];
        const float4* xs = reinterpret_cast<const float4*>(obj + (size_t)s * D_DIM);
        v1 = __ldg(xs + lane);
    }

    float4 acc;
    acc.x = fmaf(v1.x, ds, a.x * dn);
    acc.y = fmaf(v1.y, ds, a.y * dn);
    acc.z = fmaf(v1.z, ds, a.z * dn);
    acc.w = fmaf(v1.w, ds, a.w * dn);

    // group 2: batched bucket gathers, up to 8 in flight
    if (n < O_NUM) {
        int beg = g_offs[n];
        int cnt = g_offs[n + 1] - beg;
        for (int bb = 0; bb < cnt; bb += 8) {
            int m = cnt - bb; if (m > 8) m = 8;
            int   kid = 0;
            float dkl = 0.0f;
            if (lane < m) {
                kid = g_sorted[beg + bb + lane];
                dkl = (kid < O_NUM) ? g_dinv[kid] : RSQRT2F;
            }
            #pragma unroll
            for (int i = 0; i < 8; i++) {
                if (i >= m) break;
                int   k  = __shfl_sync(0xFFFFFFFFu, kid, i);
                float dk = __shfl_sync(0xFFFFFFFFu, dkl, i);
                const float4* xk = reinterpret_cast<const float4*>(row_ptr(k, obj, pred));
                float4 v = __ldg(xk + lane);
                acc.x = fmaf(v.x, dk, acc.x);
                acc.y = fmaf(v.y, dk, acc.y);
                acc.z = fmaf(v.z, dk, acc.z);
                acc.w = fmaf(v.w, dk, acc.w);
            }
        }
    }

    acc.x *= dn; acc.y *= dn; acc.z *= dn; acc.w *= dn;

    float v4[4] = {acc.x, acc.y, acc.z, acc.w};
    alignas(8) __nv_bfloat16 h[4];
    alignas(8) __nv_bfloat16 l[4];
    #pragma unroll
    for (int i = 0; i < 4; i++) {
        h[i] = __float2bfloat16(v4[i]);
        l[i] = __float2bfloat16(v4[i] - __bfloat162float(h[i]));
    }
    size_t base = (size_t)n * D_DIM + lane * 4;
    *reinterpret_cast<uint2*>(g_yh + base) = *reinterpret_cast<const uint2*>(h);
    *reinterpret_cast<uint2*>(g_yl + base) = *reinterpret_cast<const uint2*>(l);
}

// ---------------- K7: out = Y @ W^T + b  via bf16-split mma, smem-staged ----------------
__device__ __forceinline__ void mma16816(float c[4], const uint32_t a[4], const uint32_t b[2]) {
    asm("mma.sync.aligned.m16n8k16.row.col.f32.bf16.bf16.f32 "
        "{%0,%1,%2,%3}, {%4,%5,%6,%7}, {%8,%9}, {%0,%1,%2,%3};"
        : "+f"(c[0]), "+f"(c[1]), "+f"(c[2]), "+f"(c[3])
        : "r"(a[0]), "r"(a[1]), "r"(a[2]), "r"(a[3]), "r"(b[0]), "r"(b[1]));
}

#define LDSY 136
#define TILE_BYTES (128 * LDSY * 2)

__device__ __forceinline__ uint32_t lds32(const __nv_bfloat16* p) {
    return *reinterpret_cast<const uint32_t*>(p);
}

extern __shared__ char sm_raw[];

__global__ __launch_bounds__(256) void gemm_mma_kernel(const float* __restrict__ bias,
                                                       float* __restrict__ out) {
    __nv_bfloat16* sYh = reinterpret_cast<__nv_bfloat16*>(sm_raw);
    __nv_bfloat16* sYl = sYh + 128 * LDSY;
    __nv_bfloat16* sWh = sYl + 128 * LDSY;
    __nv_bfloat16* sWl = sWh + 128 * LDSY;

    int tid  = threadIdx.x;
    int warp = tid >> 5, lane = tid & 31;
    int g  = lane >> 2;
    int tg = lane & 3;
    int rowbase = blockIdx.x * 128;

    #pragma unroll
    for (int it = 0; it < 8; it++) {
        int r = it * 16 + (tid >> 4);
        int cseg = tid & 15;
        uint4 vh = *reinterpret_cast<const uint4*>(g_wh + r * D_DIM + cseg * 8);
        uint4 vl = *reinterpret_cast<const uint4*>(g_wl + r * D_DIM + cseg * 8);
        *reinterpret_cast<uint4*>(sWh + r * LDSY + cseg * 8) = vh;
        *reinterpret_cast<uint4*>(sWl + r * LDSY + cseg * 8) = vl;
    }
    #pragma unroll
    for (int it = 0; it < 8; it++) {
        int r = it * 16 + (tid >> 4);
        int cseg = tid & 15;
        int grow = rowbase + r;
        uint4 vh = make_uint4(0u, 0u, 0u, 0u), vl = vh;
        if (grow < N_NUM) {
            vh = *reinterpret_cast<const uint4*>(g_yh + (size_t)grow * D_DIM + cseg * 8);
            vl = *reinterpret_cast<const uint4*>(g_yl + (size_t)grow * D_DIM + cseg * 8);
        }
        *reinterpret_cast<uint4*>(sYh + r * LDSY + cseg * 8) = vh;
        *reinterpret_cast<uint4*>(sYl + r * LDSY + cseg * 8) = vl;
    }
    __syncthreads();

    const __nv_bfloat16* aH0 = sYh + (warp * 16 + g) * LDSY;
    const __nv_bfloat16* aL0 = sYl + (warp * 16 + g) * LDSY;

    float c[16][4];
    #pragma unroll
    for (int n = 0; n < 16; n++)
        #pragma unroll
        for (int q = 0; q < 4; q++) c[n][q] = 0.0f;

    #pragma unroll
    for (int kt = 0; kt < 8; kt++) {
        int k = kt * 16;
        uint32_t ah[4], al[4];
        ah[0] = lds32(aH0 + k + tg * 2);
        ah[1] = lds32(aH0 + 8 * LDSY + k + tg * 2);
        ah[2] = lds32(aH0 + k + 8 + tg * 2);
        ah[3] = lds32(aH0 + 8 * LDSY + k + 8 + tg * 2);
        al[0] = lds32(aL0 + k + tg * 2);
        al[1] = lds32(aL0 + 8 * LDSY + k + tg * 2);
        al[2] = lds32(aL0 + k + 8 + tg * 2);
        al[3] = lds32(aL0 + 8 * LDSY + k + 8 + tg * 2);

        #pragma unroll
        for (int n = 0; n < 16; n++) {
            const __nv_bfloat16* bH = sWh + (n * 8 + g) * LDSY + k + tg * 2;
            const __nv_bfloat16* bL = sWl + (n * 8 + g) * LDSY + k + tg * 2;
            uint32_t bh[2] = { lds32(bH), lds32(bH + 8) };
            uint32_t bl[2] = { lds32(bL), lds32(bL + 8) };
            mma16816(c[n], ah, bh);
            mma16816(c[n], al, bh);
            mma16816(c[n], ah, bl);
        }
    }

    int r0 = rowbase + warp * 16 + g;
    int r1 = r0 + 8;
    #pragma unroll
    for (int n = 0; n < 16; n++) {
        int col = n * 8 + tg * 2;
        float2 bb = *reinterpret_cast<const float2*>(bias + col);
        if (r0 < N_NUM) {
            float2 o = make_float2(c[n][0] + bb.x, c[n][1] + bb.y);
            *reinterpret_cast<float2*>(out + (size_t)r0 * D_DIM + col) = o;
        }
        if (r1 < N_NUM) {
            float2 o = make_float2(c[n][2] + bb.x, c[n][3] + bb.y);
            *reinterpret_cast<float2*>(out + (size_t)r1 * D_DIM + col) = o;
        }
    }
}

// ---------------- launch ----------------
extern "C" void kernel_launch(void* const* d_in, const int* in_sizes, int n_in,
                              void* d_out, int out_size) {
    const float* obj   = (const float*)d_in[0];
    const float* pred  = (const float*)d_in[1];
    const int*   e32   = (const int*)d_in[2];
    const float* W     = (const float*)d_in[3];
    const float* bias  = (const float*)d_in[4];
    float*       out   = (float*)d_out;

    cudaFuncSetAttribute(gemm_mma_kernel,
                         cudaFuncAttributeMaxDynamicSharedMemorySize, 4 * TILE_BYTES);

    prep_kernel<<<NPART + WBLK + 1, 256>>>(W, e32);                 // launch 1
    hist_kernel<<<(T_NUM + 255) / 256, 256>>>(e32);                 // launch 2
    scan_block_kernel<<<NPART, 256>>>();                            // launch 3
    scan_fix_kernel<<<NPART, 256>>>();                              // launch 4
    csr_scatter_kernel<<<(T_NUM + 255) / 256, 256>>>(e32);          // launch 5
    aggregate_kernel<<<(N_NUM + 7) / 8, 256>>>(obj, pred, e32);     // launch 6  <- ncu -s 5
    gemm_mma_kernel<<<(N_NUM + 127) / 128, 256, 4 * TILE_BYTES>>>(bias, out);  // launch 7
}